// round 16
// baseline (speedup 1.0000x reference)
#include <cuda_runtime.h>
#include <math.h>
#include <float.h>

#define BB    2
#define NPTS  8192
#define HALFN 4096
#define KNN   16
#define KP1   17
#define C1    16
#define CC    64
#define ROWS1 (BB*NPTS*KNN)   /* 262144 edge rows */
#define ROWS2 (BB*NPTS)       /* 16384 point rows */
#define FULLW 0xffffffffu
#define IMAXS 0x7fffffff

// ---------------- scratch (static device globals; no runtime allocs) ----------------
__device__ float4 g_p4[ROWS2];                      // packed (x,y,z,|p|^2)
__device__ int    g_nbr[ROWS2*KP1];                 // sorted knn indices (incl. self at 0)
__device__ float  g_pd [ROWS2*2*KP1];               // per-half top-17 distances
__device__ int    g_pi [ROWS2*2*KP1];               // per-half top-17 indices
__device__ float  g_y1a[(size_t)C1*ROWS1];          // [c][row] pre-BN layer1a
__device__ float  g_y1b[(size_t)CC*ROWS1];          // [c][row] pre-BN layer1b
__device__ float  g_pool[(size_t)CC*ROWS2];         // [c][bn]  pooled (post relu)
__device__ float  g_y2 [(size_t)CC*ROWS2];          // [c][bn]  pre-BN point branch
__device__ float  g_y3 [(size_t)CC*ROWS2];          // [c][bn]  pre-BN final
__device__ float  g_acc[512];                       // per-group sums: base g*128 (+64 = sumsq)
__device__ float  g_mr [512];                       // per-group folded scale(+0)/shift(+64)

// ---------------- kernels ----------------
__global__ void k_zero() { g_acc[threadIdx.x] = 0.0f; }

__global__ void k_prep(const float* __restrict__ pts) {
    int i = blockIdx.x*blockDim.x + threadIdx.x;
    if (i < ROWS2) {
        float x = pts[3*i], y = pts[3*i+1], z = pts[3*i+2];
        g_p4[i] = make_float4(x, y, z, x*x + y*y + z*z);
    }
}

__device__ __forceinline__ bool lexless(float d0, int i0, float d1, int i1) {
    return d0 < d1 || (d0 == d1 && i0 < i1);
}

// shifted distance d' = |p|^2 - 2 q.p  (= d2 - |q|^2, monotone in d2): 3 FMAs
__device__ __forceinline__ float sdist(const float3 nq, const float4 p) {
    return fmaf(nq.x, p.x, fmaf(nq.y, p.y, fmaf(nq.z, p.z, p.w)));
}

// ascending bitonic sort of one float per lane across the warp (values only)
__device__ __forceinline__ void bsort32f(float& d, int lane) {
    #pragma unroll
    for (int k = 2; k <= 32; k <<= 1) {
        #pragma unroll
        for (int j = k >> 1; j > 0; j >>= 1) {
            float od = __shfl_xor_sync(FULLW, d, j);
            bool keepMin = (((lane & j) == 0) == ((lane & k) == 0));
            if (keepMin ? (od < d) : (od > d)) d = od;
        }
    }
}

// warp-distributed sorted-list insert (lex order), fixed capacity 32 (use 17)
__device__ __forceinline__ void ins17(float dc, int jc, float& ld, int& li, int lane) {
    unsigned lessm = __ballot_sync(FULLW, lexless(ld, li, dc, jc));
    int pos = __popc(lessm);
    float pd = __shfl_up_sync(FULLW, ld, 1);
    int   pi = __shfl_up_sync(FULLW, li, 1);
    if (lane > pos)       { ld = pd; li = pi; }
    else if (lane == pos) { ld = dc; li = jc; }
}

// exact warp-distributed top-17 with running threshold — fallback path
__device__ __forceinline__ void insert_warp(unsigned mask, float d, int j,
        float& ld, int& li, float& thrd, int& thri, int lane) {
    while (mask) {
        int s = __ffs(mask) - 1;
        mask &= mask - 1;
        float dc = __shfl_sync(FULLW, d, s);
        int   jc = __shfl_sync(FULLW, j, s);
        if (lexless(dc, jc, thrd, thri)) {
            unsigned lessm = __ballot_sync(FULLW, lexless(ld, li, dc, jc));
            int pos = __popc(lessm);
            float pd = __shfl_up_sync(FULLW, ld, 1);
            int   pi = __shfl_up_sync(FULLW, li, 1);
            if (lane > pos)       { ld = pd; li = pi; }
            else if (lane == pos) { ld = dc; li = jc; }
            thrd = __shfl_sync(FULLW, ld, KP1-1);
            thri = __shfl_sync(FULLW, li, KP1-1);
        }
    }
}

// split-candidate brute-force top-17: block = (query-group of 64, candidate half
// of 4096). 64 KB smem -> 2 blocks/SM resident; block work = half scan, so the
// fractional-wave tail costs half as much. Per-half exact lex top-17 written to
// g_pd/g_pi; k_mrg merges the two disjoint halves into the global top-17.
__global__ void __launch_bounds__(1024, 2) k_knn() {
    extern __shared__ float4 sp[];
    const int tid = threadIdx.x;
    const int h = blockIdx.x & 1;
    const int g = blockIdx.x >> 1;
    const int blocksPerBatch = NPTS/64;             // 128 query-groups per batch
    const int b = g / blocksPerBatch;
    const int qbase = (g % blocksPerBatch) * 64;
    const int joff = h*HALFN;

    for (int i = tid; i < HALFN; i += 1024) sp[i] = g_p4[b*NPTS + joff + i];
    __syncthreads();

    const int w = tid >> 5, lane = tid & 31;
    const int q0 = qbase + 2*w, q1 = q0 + 1;
    const float4 qa = g_p4[b*NPTS + q0], qb = g_p4[b*NPTS + q1];
    const float3 na = make_float3(-2.0f*qa.x, -2.0f*qa.y, -2.0f*qa.z);
    const float3 nb = make_float3(-2.0f*qb.x, -2.0f*qb.y, -2.0f*qb.z);

    // ---- Pass A: per-lane min of shifted distance, stride-1 loads ----
    float m0d = FLT_MAX, m1d = FLT_MAX;
    for (int base = 0; base < HALFN; base += 64) {
        float4 pA = sp[base + lane];
        float4 pB = sp[base + 32 + lane];
        m0d = fminf(m0d, fminf(sdist(na, pA), sdist(na, pB)));
        m1d = fminf(m1d, fminf(sdist(nb, pA), sdist(nb, pB)));
    }

    // ---- thresholds: 17th smallest lane-min per query ----
    float t0d, t1d;
    {
        float d = m0d;
        bsort32f(d, lane);
        t0d = __shfl_sync(FULLW, d, KP1-1);
        d = m1d;
        bsort32f(d, lane);
        t1d = __shfl_sync(FULLW, d, KP1-1);
    }

    // ---- Pass B: collect all candidates with d' <= T, stride-1 loads ----
    float ld0 = FLT_MAX, ld1 = FLT_MAX; int li0 = IMAXS, li1 = IMAXS;
    int cnt0 = 0, cnt1 = 0;
    for (int base = 0; base < HALFN; base += 64) {
        float4 pA = sp[base + lane];
        float4 pB = sp[base + 32 + lane];
        float dA0 = sdist(na, pA), dB0 = sdist(na, pB);
        float dA1 = sdist(nb, pA), dB1 = sdist(nb, pB);
        unsigned mq0 = __ballot_sync(FULLW, (dA0 <= t0d) | (dB0 <= t0d));
        unsigned mq1 = __ballot_sync(FULLW, (dA1 <= t1d) | (dB1 <= t1d));
        if (!(mq0 | mq1)) continue;
        while (mq0) {
            int s = __ffs(mq0) - 1; mq0 &= mq0 - 1;
            float dAc = __shfl_sync(FULLW, dA0, s);
            float dBc = __shfl_sync(FULLW, dB0, s);
            int jAc = joff + base + s, jBc = joff + base + 32 + s;
            if (dAc <= t0d) { ins17(dAc, jAc, ld0, li0, lane); ++cnt0; }
            if (dBc <= t0d) { ins17(dBc, jBc, ld0, li0, lane); ++cnt0; }
        }
        while (mq1) {
            int s = __ffs(mq1) - 1; mq1 &= mq1 - 1;
            float dAc = __shfl_sync(FULLW, dA1, s);
            float dBc = __shfl_sync(FULLW, dB1, s);
            int jAc = joff + base + s, jBc = joff + base + 32 + s;
            if (dAc <= t1d) { ins17(dAc, jAc, ld1, li1, lane); ++cnt1; }
            if (dBc <= t1d) { ins17(dBc, jBc, ld1, li1, lane); ++cnt1; }
        }
    }

    // ---- store per-half lists (cnt>=17 by witness construction; rescan net) ----
    int q0s = ((b*NPTS + q0)*2 + h)*KP1;
    int q1s = ((b*NPTS + q1)*2 + h)*KP1;
    if (cnt0 < KP1) {
        float ld = FLT_MAX; int li = IMAXS; float td = FLT_MAX; int ti = IMAXS;
        for (int j = lane; j < HALFN; j += 32) {
            float d = sdist(na, sp[j]);
            unsigned m = __ballot_sync(FULLW, lexless(d, joff + j, td, ti));
            if (m) insert_warp(m, d, joff + j, ld, li, td, ti, lane);
        }
        ld0 = ld; li0 = li;
    }
    if (cnt1 < KP1) {
        float ld = FLT_MAX; int li = IMAXS; float td = FLT_MAX; int ti = IMAXS;
        for (int j = lane; j < HALFN; j += 32) {
            float d = sdist(nb, sp[j]);
            unsigned m = __ballot_sync(FULLW, lexless(d, joff + j, td, ti));
            if (m) insert_warp(m, d, joff + j, ld, li, td, ti, lane);
        }
        ld1 = ld; li1 = li;
    }
    if (lane < KP1) {
        g_pd[q0s + lane] = ld0; g_pi[q0s + lane] = li0;
        g_pd[q1s + lane] = ld1; g_pi[q1s + lane] = li1;
    }
}

// merge the two per-half sorted top-17 lists into the global top-17 (warp/query)
__global__ void __launch_bounds__(256) k_mrg() {
    int q = blockIdx.x*8 + (threadIdx.x >> 5);
    int lane = threadIdx.x & 31;
    float ld = FLT_MAX; int li = IMAXS;
    if (lane < KP1) {
        ld = g_pd[(q*2 + 0)*KP1 + lane];
        li = g_pi[(q*2 + 0)*KP1 + lane];
    }
    float thrd = __shfl_sync(FULLW, ld, KP1-1);
    int   thri = __shfl_sync(FULLW, li, KP1-1);
    #pragma unroll
    for (int s = 0; s < KP1; ++s) {
        float dc = g_pd[(q*2 + 1)*KP1 + s];   // uniform -> broadcast load
        int   jc = g_pi[(q*2 + 1)*KP1 + s];
        if (!lexless(dc, jc, thrd, thri)) break;   // both lists sorted ascending
        ins17(dc, jc, ld, li, lane);
        thrd = __shfl_sync(FULLW, ld, KP1-1);
        thri = __shfl_sync(FULLW, li, KP1-1);
    }
    if (lane < KP1) g_nbr[q*KP1 + lane] = li;
}

// warp butterfly + block fold + one atomic per channel per block.
// vals[NCH] per thread; 8 warps; caller provides smem[2*8*NCH].
template<int NCH>
__device__ __forceinline__ void block_stats(const float* vals, float* red,
                                            int t, int accBase) {
    int w = t >> 5, lane = t & 31;
    float* ssum = red;
    float* ssq  = red + 8*NCH;
    #pragma unroll
    for (int c = 0; c < NCH; ++c) {
        float s = vals[c], q = vals[c]*vals[c];
        #pragma unroll
        for (int off = 16; off; off >>= 1) {
            s += __shfl_xor_sync(FULLW, s, off);
            q += __shfl_xor_sync(FULLW, q, off);
        }
        if (lane == 0) { ssum[w*NCH + c] = s; ssq[w*NCH + c] = q; }
    }
    __syncthreads();
    if (t < NCH) {
        float a = 0.0f, a2 = 0.0f;
        #pragma unroll
        for (int i = 0; i < 8; ++i) { a += ssum[i*NCH + t]; a2 += ssq[i*NCH + t]; }
        atomicAdd(&g_acc[accBase + t], a);
        atomicAdd(&g_acc[accBase + 64 + t], a2);
    }
}

// edge features (7) -> 16, store pre-BN channel-major, stats fused
__global__ void __launch_bounds__(256) k_l1a(const float* __restrict__ W1a) {
    __shared__ float sw[C1*7];
    __shared__ float red[2*8*C1];
    int t = threadIdx.x;
    if (t < C1*7) sw[t] = W1a[t];
    __syncthreads();
    int row = blockIdx.x*blockDim.x + t;
    int bn = row >> 4, k = row & 15;
    int b = bn >> 13;
    int i0 = g_nbr[bn*KP1];
    int in = g_nbr[bn*KP1 + 1 + k];
    float4 p0 = g_p4[b*NPTS + i0];
    float4 pn = g_p4[b*NPTS + in];
    float f[7];
    f[0] = p0.x; f[1] = p0.y; f[2] = p0.z;
    float rx = pn.x - p0.x, ry = pn.y - p0.y, rz = pn.z - p0.z;
    f[3] = rx; f[4] = ry; f[5] = rz;
    f[6] = sqrtf(rx*rx + ry*ry + rz*rz + 1e-8f);
    float a[C1];
    #pragma unroll
    for (int c = 0; c < C1; ++c) {
        float s = 0.0f;
        #pragma unroll
        for (int j = 0; j < 7; ++j) s += f[j]*sw[c*7 + j];
        a[c] = s;
        g_y1a[(size_t)c*ROWS1 + row] = s;
    }
    block_stats<C1>(a, red, t, 0);
}

// fold BN into scale/shift:  y_bn = y*scale + shift
__global__ void k_fin(int base, float inv_cnt, int nch,
                      const float* __restrict__ gamma, const float* __restrict__ beta) {
    int c = threadIdx.x;
    if (c < nch) {
        float mean = g_acc[base + c]*inv_cnt;
        float var  = g_acc[base + 64 + c]*inv_cnt - mean*mean;
        float r = rsqrtf(var + 1e-5f);
        float sc = r*gamma[c];
        g_mr[base + c]      = sc;
        g_mr[base + 64 + c] = beta[c] - mean*sc;
    }
}

// bn+relu(layer1a) -> 16x64 matmul, store pre-BN channel-major, stats fused
__global__ void __launch_bounds__(256) k_l1b(const float* __restrict__ W1b) {
    __shared__ float wt[C1*CC];     // wt[j*64+c]
    __shared__ float sc0[C1], sh0[C1];
    __shared__ float red[2*8*CC];
    int t = threadIdx.x;
    for (int i = t; i < C1*CC; i += blockDim.x) {
        int c = i / C1, j = i % C1;
        wt[j*CC + c] = W1b[i];
    }
    if (t < C1) { sc0[t] = g_mr[t]; sh0[t] = g_mr[64 + t]; }
    __syncthreads();
    int row = blockIdx.x*blockDim.x + t;
    float acc[CC];
    #pragma unroll
    for (int c = 0; c < CC; ++c) acc[c] = 0.0f;
    #pragma unroll
    for (int j = 0; j < C1; ++j) {
        float x = g_y1a[(size_t)j*ROWS1 + row];
        x = fmaxf(x*sc0[j] + sh0[j], 0.0f);
        #pragma unroll
        for (int c = 0; c < CC; ++c) acc[c] += x*wt[j*CC + c];
    }
    #pragma unroll
    for (int c = 0; c < CC; ++c) g_y1b[(size_t)c*ROWS1 + row] = acc[c];
    block_stats<CC>(acc, red, t, 128);
}

// point branch 3 -> 64 (pre-BN), stats fused
__global__ void __launch_bounds__(256) k_pts(const float* __restrict__ W2) {
    __shared__ float sw[CC*3];
    __shared__ float red[2*8*CC];
    int t = threadIdx.x;
    if (t < CC*3) sw[t] = W2[t];
    __syncthreads();
    int bn = blockIdx.x*blockDim.x + t;
    float4 p = g_p4[bn];
    float y[CC];
    #pragma unroll
    for (int c = 0; c < CC; ++c) {
        float a = p.x*sw[c*3] + p.y*sw[c*3+1] + p.z*sw[c*3+2];
        y[c] = a;
        g_y2[(size_t)c*ROWS2 + bn] = a;
    }
    block_stats<CC>(y, red, t, 256);
}

// bn+relu(layer1b) then max over K
__global__ void k_pool() {
    int c = blockIdx.y;
    int bn = blockIdx.x*blockDim.x + threadIdx.x;
    float sc = g_mr[128 + c], sh = g_mr[128 + 64 + c];
    const float4* p = (const float4*)(g_y1b + (size_t)c*ROWS1 + (size_t)bn*KNN);
    float m = -FLT_MAX;
    #pragma unroll
    for (int i = 0; i < 4; ++i) {
        float4 v = p[i];
        m = fmaxf(m, fmaxf(0.0f, v.x*sc + sh));
        m = fmaxf(m, fmaxf(0.0f, v.y*sc + sh));
        m = fmaxf(m, fmaxf(0.0f, v.z*sc + sh));
        m = fmaxf(m, fmaxf(0.0f, v.w*sc + sh));
    }
    g_pool[(size_t)c*ROWS2 + bn] = m;
}

// concat(bn+relu(y2), pool) -> 128x64 matmul, pre-BN channel-major,
// with y3 per-channel sum/sumsq fused
__global__ void k_l3(const float* __restrict__ W3) {
    extern __shared__ float smem[];
    float* sw  = smem;               // [128][65] -> sw[j*65+c]
    float* sin = smem + 128*65;      // [128][32] -> sin[j*32+bnl]
    int t = threadIdx.x;             // 256
    for (int i = t; i < 64*128; i += 256) {
        int c = i >> 7, j = i & 127;
        sw[j*65 + c] = W3[i];
    }
    int bn0 = blockIdx.x * 32;
    for (int e = t; e < 128*32; e += 256) {
        int j = e >> 5, bnl = e & 31;
        float v;
        if (j < 64) {
            v = g_y2[(size_t)j*ROWS2 + bn0 + bnl];
            v = fmaxf(v*g_mr[256 + j] + g_mr[256 + 64 + j], 0.0f);
        } else {
            v = g_pool[(size_t)(j - 64)*ROWS2 + bn0 + bnl];
        }
        sin[e] = v;
    }
    __syncthreads();
    int tx = t & 31, ty = t >> 5;
    float acc[8];
    #pragma unroll
    for (int i = 0; i < 8; ++i) acc[i] = 0.0f;
    for (int j = 0; j < 128; ++j) {
        float x = sin[j*32 + tx];
        #pragma unroll
        for (int i = 0; i < 8; ++i) acc[i] += x*sw[j*65 + ty*8 + i];
    }
    #pragma unroll
    for (int i = 0; i < 8; ++i)
        g_y3[(size_t)(ty*8 + i)*ROWS2 + bn0 + tx] = acc[i];
    float s[8], q2[8];
    #pragma unroll
    for (int i = 0; i < 8; ++i) { s[i] = acc[i]; q2[i] = acc[i]*acc[i]; }
    #pragma unroll
    for (int off = 16; off; off >>= 1) {
        #pragma unroll
        for (int i = 0; i < 8; ++i) {
            s[i]  += __shfl_xor_sync(FULLW, s[i],  off);
            q2[i] += __shfl_xor_sync(FULLW, q2[i], off);
        }
    }
    if (tx == 0) {
        #pragma unroll
        for (int i = 0; i < 8; ++i) {
            atomicAdd(&g_acc[384 + ty*8 + i], s[i]);
            atomicAdd(&g_acc[384 + 64 + ty*8 + i], q2[i]);
        }
    }
}

// bn+relu(final) + transpose to row-major output (B,N,64)
__global__ void k_out(float* __restrict__ out) {
    __shared__ float s[64*33];
    int t = threadIdx.x;
    int bn0 = blockIdx.x*32;
    for (int e = t; e < 2048; e += 256) {
        int c = e >> 5, bnl = e & 31;
        float v = g_y3[(size_t)c*ROWS2 + bn0 + bnl];
        v = fmaxf(v*g_mr[384 + c] + g_mr[384 + 64 + c], 0.0f);
        s[c*33 + bnl] = v;
    }
    __syncthreads();
    for (int e = t; e < 2048; e += 256) {
        int bnl = e >> 6, c = e & 63;
        out[(size_t)(bn0 + bnl)*64 + c] = s[c*33 + bnl];
    }
}

// ---------------- launch ----------------
extern "C" void kernel_launch(void* const* d_in, const int* in_sizes, int n_in,
                              void* d_out, int out_size) {
    const float* pts = (const float*)d_in[0];
    const float* W1a = (const float*)d_in[1];
    const float* g1a = (const float*)d_in[2];
    const float* b1a = (const float*)d_in[3];
    const float* W1b = (const float*)d_in[4];
    const float* g1b = (const float*)d_in[5];
    const float* b1b = (const float*)d_in[6];
    const float* W2  = (const float*)d_in[7];
    const float* g2  = (const float*)d_in[8];
    const float* b2  = (const float*)d_in[9];
    const float* W3  = (const float*)d_in[10];
    const float* g3  = (const float*)d_in[11];
    const float* b3  = (const float*)d_in[12];
    float* out = (float*)d_out;

    (void)in_sizes; (void)n_in; (void)out_size;

    cudaFuncSetAttribute(k_knn, cudaFuncAttributeMaxDynamicSharedMemorySize,
                         HALFN*(int)sizeof(float4));
    cudaFuncSetAttribute(k_l3, cudaFuncAttributeMaxDynamicSharedMemorySize,
                         (128*65 + 128*32)*(int)sizeof(float));

    k_zero<<<1, 512>>>();
    k_prep<<<(ROWS2 + 255)/256, 256>>>(pts);
    k_knn<<<BB*(NPTS/64)*2, 1024, HALFN*(int)sizeof(float4)>>>();
    k_mrg<<<ROWS2/8, 256>>>();

    k_l1a<<<ROWS1/256, 256>>>(W1a);
    k_fin<<<1, 64>>>(0, 1.0f/(float)ROWS1, 16, g1a, b1a);

    k_l1b<<<ROWS1/256, 256>>>(W1b);
    k_fin<<<1, 64>>>(128, 1.0f/(float)ROWS1, 64, g1b, b1b);

    k_pts<<<ROWS2/256, 256>>>(W2);
    k_fin<<<1, 64>>>(256, 1.0f/(float)ROWS2, 64, g2, b2);

    k_pool<<<dim3(ROWS2/256, 64), 256>>>();

    k_l3<<<ROWS2/32, 256, (128*65 + 128*32)*(int)sizeof(float)>>>(W3);
    k_fin<<<1, 64>>>(384, 1.0f/(float)ROWS2, 64, g3, b3);

    k_out<<<ROWS2/32, 256>>>(out);
}

// round 17
// speedup vs baseline: 1.0787x; 1.0787x over previous
#include <cuda_runtime.h>
#include <math.h>
#include <float.h>

#define BB    2
#define NPTS  8192
#define KNN   16
#define KP1   17
#define C1    16
#define CC    64
#define ROWS1 (BB*NPTS*KNN)   /* 262144 edge rows */
#define ROWS2 (BB*NPTS)       /* 16384 point rows */
#define FULLW 0xffffffffu
#define IMAXS 0x7fffffff

// ---------------- scratch (static device globals; no runtime allocs) ----------------
__device__ float4 g_p4[ROWS2];                      // packed (x,y,z,|p|^2)
__device__ int    g_nbr[ROWS2*KP1];                 // sorted knn indices (incl. self at 0)
__device__ float  g_y1a[(size_t)C1*ROWS1];          // [c][row] pre-BN layer1a
__device__ float  g_y1b[(size_t)CC*ROWS1];          // [c][row] pre-BN layer1b
__device__ float  g_pool[(size_t)CC*ROWS2];         // [c][bn]  pooled (post relu)
__device__ float  g_y2 [(size_t)CC*ROWS2];          // [c][bn]  pre-BN point branch
__device__ float  g_y3 [(size_t)CC*ROWS2];          // [c][bn]  pre-BN final
__device__ float  g_acc[512];                       // per-group sums: base g*128 (+64 = sumsq)
__device__ float  g_mr [512];                       // per-group folded scale(+0)/shift(+64)

// ---------------- kernels ----------------
__global__ void k_zero() { g_acc[threadIdx.x] = 0.0f; }

__global__ void k_prep(const float* __restrict__ pts) {
    int i = blockIdx.x*blockDim.x + threadIdx.x;
    if (i < ROWS2) {
        float x = pts[3*i], y = pts[3*i+1], z = pts[3*i+2];
        g_p4[i] = make_float4(x, y, z, x*x + y*y + z*z);
    }
}

__device__ __forceinline__ bool lexless(float d0, int i0, float d1, int i1) {
    return d0 < d1 || (d0 == d1 && i0 < i1);
}

// shifted distance d' = |p|^2 - 2 q.p  (= d2 - |q|^2, monotone in d2): 3 FMAs
__device__ __forceinline__ float sdist(const float3 nq, const float4 p) {
    return fmaf(nq.x, p.x, fmaf(nq.y, p.y, fmaf(nq.z, p.z, p.w)));
}

// ascending bitonic sort of one float per lane across the warp (values only)
__device__ __forceinline__ void bsort32f(float& d, int lane) {
    #pragma unroll
    for (int k = 2; k <= 32; k <<= 1) {
        #pragma unroll
        for (int j = k >> 1; j > 0; j >>= 1) {
            float od = __shfl_xor_sync(FULLW, d, j);
            bool keepMin = (((lane & j) == 0) == ((lane & k) == 0));
            if (keepMin ? (od < d) : (od > d)) d = od;
        }
    }
}

// warp-distributed sorted-list insert (lex order), fixed capacity 32 (use 17)
__device__ __forceinline__ void ins17(float dc, int jc, float& ld, int& li, int lane) {
    unsigned lessm = __ballot_sync(FULLW, lexless(ld, li, dc, jc));
    int pos = __popc(lessm);
    float pd = __shfl_up_sync(FULLW, ld, 1);
    int   pi = __shfl_up_sync(FULLW, li, 1);
    if (lane > pos)       { ld = pd; li = pi; }
    else if (lane == pos) { ld = dc; li = jc; }
}

// exact warp-distributed top-17 with running threshold — fallback path
__device__ __forceinline__ void insert_warp(unsigned mask, float d, int j,
        float& ld, int& li, float& thrd, int& thri, int lane) {
    while (mask) {
        int s = __ffs(mask) - 1;
        mask &= mask - 1;
        float dc = __shfl_sync(FULLW, d, s);
        int   jc = __shfl_sync(FULLW, j, s);
        if (lexless(dc, jc, thrd, thri)) {
            unsigned lessm = __ballot_sync(FULLW, lexless(ld, li, dc, jc));
            int pos = __popc(lessm);
            float pd = __shfl_up_sync(FULLW, ld, 1);
            int   pi = __shfl_up_sync(FULLW, li, 1);
            if (lane > pos)       { ld = pd; li = pi; }
            else if (lane == pos) { ld = dc; li = jc; }
            thrd = __shfl_sync(FULLW, ld, KP1-1);
            thri = __shfl_sync(FULLW, li, KP1-1);
        }
    }
}

// brute-force top-17, 4 queries/warp, two-pass fixed-threshold scheme.
// 128 queries/block -> 128 blocks total: SINGLE wave on the chip, and each
// candidate LDS serves 4 queries (half the crossbar cycles per query vs QPW=2).
// Lane candidate partition is unchanged, so thresholds/neighbor sets are
// identical to the QPW=2 version.
__global__ void __launch_bounds__(1024, 1) k_knn() {
    extern __shared__ float4 sp[];
    const int tid = threadIdx.x;
    const int blocksPerBatch = NPTS/128;            // 64 blocks per batch
    const int b = blockIdx.x / blocksPerBatch;
    const int qbase = (blockIdx.x % blocksPerBatch) * 128;

    for (int i = tid; i < NPTS; i += 1024) sp[i] = g_p4[b*NPTS + i];
    __syncthreads();

    const int w = tid >> 5, lane = tid & 31;
    const int qq = qbase + w*4;

    float3 nq[4];
    #pragma unroll
    for (int i = 0; i < 4; ++i) {
        float4 q = sp[qq + i];
        nq[i] = make_float3(-2.0f*q.x, -2.0f*q.y, -2.0f*q.z);
    }

    // ---- Pass A: per-lane min of shifted distance, stride-1 loads ----
    float m[4];
    #pragma unroll
    for (int i = 0; i < 4; ++i) m[i] = FLT_MAX;
    for (int base = 0; base < NPTS; base += 64) {
        float4 pA = sp[base + lane];
        float4 pB = sp[base + 32 + lane];
        #pragma unroll
        for (int i = 0; i < 4; ++i)
            m[i] = fminf(m[i], fminf(sdist(nq[i], pA), sdist(nq[i], pB)));
    }

    // ---- thresholds: 17th smallest lane-min per query ----
    float thr[4];
    #pragma unroll
    for (int i = 0; i < 4; ++i) {
        float d = m[i];
        bsort32f(d, lane);
        thr[i] = __shfl_sync(FULLW, d, KP1-1);
    }

    // ---- Pass B: collect all candidates with d' <= T, stride-1 loads ----
    float ld[4]; int li[4]; int cnt[4];
    #pragma unroll
    for (int i = 0; i < 4; ++i) { ld[i] = FLT_MAX; li[i] = IMAXS; cnt[i] = 0; }
    for (int base = 0; base < NPTS; base += 64) {
        float4 pA = sp[base + lane];
        float4 pB = sp[base + 32 + lane];
        float dA[4], dB[4];
        #pragma unroll
        for (int i = 0; i < 4; ++i) { dA[i] = sdist(nq[i], pA); dB[i] = sdist(nq[i], pB); }
        unsigned mq[4];
        #pragma unroll
        for (int i = 0; i < 4; ++i)
            mq[i] = __ballot_sync(FULLW, (dA[i] <= thr[i]) | (dB[i] <= thr[i]));
        if (!(mq[0] | mq[1] | mq[2] | mq[3])) continue;
        #pragma unroll
        for (int i = 0; i < 4; ++i) {
            unsigned mk = mq[i];
            while (mk) {
                int s = __ffs(mk) - 1; mk &= mk - 1;
                float dAc = __shfl_sync(FULLW, dA[i], s);
                float dBc = __shfl_sync(FULLW, dB[i], s);
                int jAc = base + s, jBc = base + 32 + s;
                if (dAc <= thr[i]) { ins17(dAc, jAc, ld[i], li[i], lane); ++cnt[i]; }
                if (dBc <= thr[i]) { ins17(dBc, jBc, ld[i], li[i], lane); ++cnt[i]; }
            }
        }
    }

    // ---- store (cnt>=17 holds by witness construction; exact rescan as net) ----
    #pragma unroll
    for (int i = 0; i < 4; ++i) {
        if (cnt[i] >= KP1) {
            if (lane < KP1) g_nbr[(b*NPTS + qq + i)*KP1 + lane] = li[i];
        } else {
            float rd = FLT_MAX; int ri = IMAXS; float td = FLT_MAX; int ti = IMAXS;
            for (int j = lane; j < NPTS; j += 32) {
                float d = sdist(nq[i], sp[j]);
                unsigned mk = __ballot_sync(FULLW, lexless(d, j, td, ti));
                if (mk) insert_warp(mk, d, j, rd, ri, td, ti, lane);
            }
            if (lane < KP1) g_nbr[(b*NPTS + qq + i)*KP1 + lane] = ri;
        }
    }
}

// block-wide per-channel sum/sumsq: rounds of 8 channels through smem,
// one warp reduces one channel per round. red = smem[8*256] floats.
template<int NCH>
__device__ __forceinline__ void block_stats(const float* vals, float* red,
                                            int t, int accBase) {
    int w = t >> 5, lane = t & 31;
    #pragma unroll
    for (int r = 0; r < NCH/8; ++r) {
        #pragma unroll
        for (int j = 0; j < 8; ++j) red[j*256 + t] = vals[r*8 + j];
        __syncthreads();
        float s = 0.0f, q = 0.0f;
        #pragma unroll
        for (int k = 0; k < 8; ++k) {
            float v = red[w*256 + lane + 32*k];
            s += v; q += v*v;
        }
        #pragma unroll
        for (int off = 16; off; off >>= 1) {
            s += __shfl_xor_sync(FULLW, s, off);
            q += __shfl_xor_sync(FULLW, q, off);
        }
        if (lane == 0) {
            atomicAdd(&g_acc[accBase + r*8 + w], s);
            atomicAdd(&g_acc[accBase + 64 + r*8 + w], q);
        }
        __syncthreads();
    }
}

// edge features (7) -> 16, store pre-BN channel-major, stats fused
__global__ void __launch_bounds__(256) k_l1a(const float* __restrict__ W1a) {
    __shared__ float sw[C1*7];
    __shared__ float red[8*256];
    int t = threadIdx.x;
    if (t < C1*7) sw[t] = W1a[t];
    __syncthreads();
    int row = blockIdx.x*blockDim.x + t;
    int bn = row >> 4, k = row & 15;
    int b = bn >> 13;
    int i0 = g_nbr[bn*KP1];
    int in = g_nbr[bn*KP1 + 1 + k];
    float4 p0 = g_p4[b*NPTS + i0];
    float4 pn = g_p4[b*NPTS + in];
    float f[7];
    f[0] = p0.x; f[1] = p0.y; f[2] = p0.z;
    float rx = pn.x - p0.x, ry = pn.y - p0.y, rz = pn.z - p0.z;
    f[3] = rx; f[4] = ry; f[5] = rz;
    f[6] = sqrtf(rx*rx + ry*ry + rz*rz + 1e-8f);
    float a[C1];
    #pragma unroll
    for (int c = 0; c < C1; ++c) {
        float s = 0.0f;
        #pragma unroll
        for (int j = 0; j < 7; ++j) s += f[j]*sw[c*7 + j];
        a[c] = s;
        g_y1a[(size_t)c*ROWS1 + row] = s;
    }
    block_stats<C1>(a, red, t, 0);
}

// fold BN into scale/shift:  y_bn = y*scale + shift
__global__ void k_fin(int base, float inv_cnt, int nch,
                      const float* __restrict__ gamma, const float* __restrict__ beta) {
    int c = threadIdx.x;
    if (c < nch) {
        float mean = g_acc[base + c]*inv_cnt;
        float var  = g_acc[base + 64 + c]*inv_cnt - mean*mean;
        float r = rsqrtf(var + 1e-5f);
        float sc = r*gamma[c];
        g_mr[base + c]      = sc;
        g_mr[base + 64 + c] = beta[c] - mean*sc;
    }
}

// bn+relu(layer1a) -> 16x64 matmul, store pre-BN channel-major, stats fused
__global__ void __launch_bounds__(256) k_l1b(const float* __restrict__ W1b) {
    __shared__ float wt[C1*CC];     // wt[j*64+c]
    __shared__ float sc0[C1], sh0[C1];
    __shared__ float red[8*256];
    int t = threadIdx.x;
    for (int i = t; i < C1*CC; i += blockDim.x) {
        int c = i / C1, j = i % C1;
        wt[j*CC + c] = W1b[i];
    }
    if (t < C1) { sc0[t] = g_mr[t]; sh0[t] = g_mr[64 + t]; }
    __syncthreads();
    int row = blockIdx.x*blockDim.x + t;
    float acc[CC];
    #pragma unroll
    for (int c = 0; c < CC; ++c) acc[c] = 0.0f;
    #pragma unroll
    for (int j = 0; j < C1; ++j) {
        float x = g_y1a[(size_t)j*ROWS1 + row];
        x = fmaxf(x*sc0[j] + sh0[j], 0.0f);
        #pragma unroll
        for (int c = 0; c < CC; ++c) acc[c] += x*wt[j*CC + c];
    }
    #pragma unroll
    for (int c = 0; c < CC; ++c) g_y1b[(size_t)c*ROWS1 + row] = acc[c];
    block_stats<CC>(acc, red, t, 128);
}

// point branch 3 -> 64 (pre-BN), stats fused
__global__ void __launch_bounds__(256) k_pts(const float* __restrict__ W2) {
    __shared__ float sw[CC*3];
    __shared__ float red[8*256];
    int t = threadIdx.x;
    if (t < CC*3) sw[t] = W2[t];
    __syncthreads();
    int bn = blockIdx.x*blockDim.x + t;
    float4 p = g_p4[bn];
    float y[CC];
    #pragma unroll
    for (int c = 0; c < CC; ++c) {
        float a = p.x*sw[c*3] + p.y*sw[c*3+1] + p.z*sw[c*3+2];
        y[c] = a;
        g_y2[(size_t)c*ROWS2 + bn] = a;
    }
    block_stats<CC>(y, red, t, 256);
}

// bn+relu(layer1b) then max over K
__global__ void k_pool() {
    int c = blockIdx.y;
    int bn = blockIdx.x*blockDim.x + threadIdx.x;
    float sc = g_mr[128 + c], sh = g_mr[128 + 64 + c];
    const float4* p = (const float4*)(g_y1b + (size_t)c*ROWS1 + (size_t)bn*KNN);
    float m = -FLT_MAX;
    #pragma unroll
    for (int i = 0; i < 4; ++i) {
        float4 v = p[i];
        m = fmaxf(m, fmaxf(0.0f, v.x*sc + sh));
        m = fmaxf(m, fmaxf(0.0f, v.y*sc + sh));
        m = fmaxf(m, fmaxf(0.0f, v.z*sc + sh));
        m = fmaxf(m, fmaxf(0.0f, v.w*sc + sh));
    }
    g_pool[(size_t)c*ROWS2 + bn] = m;
}

// concat(bn+relu(y2), pool) -> 128x64 matmul, pre-BN channel-major,
// with y3 per-channel sum/sumsq fused
__global__ void k_l3(const float* __restrict__ W3) {
    extern __shared__ float smem[];
    float* sw  = smem;               // [128][65] -> sw[j*65+c]
    float* sin = smem + 128*65;      // [128][32] -> sin[j*32+bnl]
    int t = threadIdx.x;             // 256
    for (int i = t; i < 64*128; i += 256) {
        int c = i >> 7, j = i & 127;
        sw[j*65 + c] = W3[i];
    }
    int bn0 = blockIdx.x * 32;
    for (int e = t; e < 128*32; e += 256) {
        int j = e >> 5, bnl = e & 31;
        float v;
        if (j < 64) {
            v = g_y2[(size_t)j*ROWS2 + bn0 + bnl];
            v = fmaxf(v*g_mr[256 + j] + g_mr[256 + 64 + j], 0.0f);
        } else {
            v = g_pool[(size_t)(j - 64)*ROWS2 + bn0 + bnl];
        }
        sin[e] = v;
    }
    __syncthreads();
    int tx = t & 31, ty = t >> 5;
    float acc[8];
    #pragma unroll
    for (int i = 0; i < 8; ++i) acc[i] = 0.0f;
    for (int j = 0; j < 128; ++j) {
        float x = sin[j*32 + tx];
        #pragma unroll
        for (int i = 0; i < 8; ++i) acc[i] += x*sw[j*65 + ty*8 + i];
    }
    #pragma unroll
    for (int i = 0; i < 8; ++i)
        g_y3[(size_t)(ty*8 + i)*ROWS2 + bn0 + tx] = acc[i];
    float s[8], q2[8];
    #pragma unroll
    for (int i = 0; i < 8; ++i) { s[i] = acc[i]; q2[i] = acc[i]*acc[i]; }
    #pragma unroll
    for (int off = 16; off; off >>= 1) {
        #pragma unroll
        for (int i = 0; i < 8; ++i) {
            s[i]  += __shfl_xor_sync(FULLW, s[i],  off);
            q2[i] += __shfl_xor_sync(FULLW, q2[i], off);
        }
    }
    if (tx == 0) {
        #pragma unroll
        for (int i = 0; i < 8; ++i) {
            atomicAdd(&g_acc[384 + ty*8 + i], s[i]);
            atomicAdd(&g_acc[384 + 64 + ty*8 + i], q2[i]);
        }
    }
}

// bn+relu(final) + transpose to row-major output (B,N,64)
__global__ void k_out(float* __restrict__ out) {
    __shared__ float s[64*33];
    int t = threadIdx.x;
    int bn0 = blockIdx.x*32;
    for (int e = t; e < 2048; e += 256) {
        int c = e >> 5, bnl = e & 31;
        float v = g_y3[(size_t)c*ROWS2 + bn0 + bnl];
        v = fmaxf(v*g_mr[384 + c] + g_mr[384 + 64 + c], 0.0f);
        s[c*33 + bnl] = v;
    }
    __syncthreads();
    for (int e = t; e < 2048; e += 256) {
        int bnl = e >> 6, c = e & 63;
        out[(size_t)(bn0 + bnl)*64 + c] = s[c*33 + bnl];
    }
}

// ---------------- launch ----------------
extern "C" void kernel_launch(void* const* d_in, const int* in_sizes, int n_in,
                              void* d_out, int out_size) {
    const float* pts = (const float*)d_in[0];
    const float* W1a = (const float*)d_in[1];
    const float* g1a = (const float*)d_in[2];
    const float* b1a = (const float*)d_in[3];
    const float* W1b = (const float*)d_in[4];
    const float* g1b = (const float*)d_in[5];
    const float* b1b = (const float*)d_in[6];
    const float* W2  = (const float*)d_in[7];
    const float* g2  = (const float*)d_in[8];
    const float* b2  = (const float*)d_in[9];
    const float* W3  = (const float*)d_in[10];
    const float* g3  = (const float*)d_in[11];
    const float* b3  = (const float*)d_in[12];
    float* out = (float*)d_out;

    (void)in_sizes; (void)n_in; (void)out_size;

    cudaFuncSetAttribute(k_knn, cudaFuncAttributeMaxDynamicSharedMemorySize,
                         NPTS*(int)sizeof(float4));
    cudaFuncSetAttribute(k_l3, cudaFuncAttributeMaxDynamicSharedMemorySize,
                         (128*65 + 128*32)*(int)sizeof(float));

    k_zero<<<1, 512>>>();
    k_prep<<<(ROWS2 + 255)/256, 256>>>(pts);
    k_knn<<<BB*(NPTS/128), 1024, NPTS*(int)sizeof(float4)>>>();

    k_l1a<<<ROWS1/256, 256>>>(W1a);
    k_fin<<<1, 64>>>(0, 1.0f/(float)ROWS1, 16, g1a, b1a);

    k_l1b<<<ROWS1/256, 256>>>(W1b);
    k_fin<<<1, 64>>>(128, 1.0f/(float)ROWS1, 64, g1b, b1b);

    k_pts<<<ROWS2/256, 256>>>(W2);
    k_fin<<<1, 64>>>(256, 1.0f/(float)ROWS2, 64, g2, b2);

    k_pool<<<dim3(ROWS2/256, 64), 256>>>();

    k_l3<<<ROWS2/32, 256, (128*65 + 128*32)*(int)sizeof(float)>>>(W3);
    k_fin<<<1, 64>>>(384, 1.0f/(float)ROWS2, 64, g3, b3);

    k_out<<<ROWS2/32, 256>>>(out);
}